// round 11
// baseline (speedup 1.0000x reference)
#include <cuda_runtime.h>
#include <cuda_fp16.h>
#include <math_constants.h>
#include <cstdint>

// ---------------- problem constants ----------------
#define B_  4
#define T_  1024
#define M_  4096          // B*T tokens
#define H_  2048
#define V_  32000

// ---------------- GEMM tiling ----------------
#define TM  128           // CTA M tile
#define TN  128           // CTA N tile (2 CTAs/SM)
#define KCH 64            // K halfs per smem stage (128B rows)
#define NSTEPS (H_/KCH)   // 32
#define NSTAGE 3
#define GRIDM (M_/TM)     // 32
#define GRIDN (V_/TN)     // 250
#define NTN 1000          // 32-col LSE partial tiles (V/32)

#define TILE_BYTES 16384u            // 128 rows x 128B, one operand, one stage
#define TILE_HALFS 8192u
#define STAGE_BYTES (2u*TILE_BYTES)  // A + B
#define SM_BIAS (NSTAGE*STAGE_BYTES) // 98304
#define SM_MBAR (SM_BIAS + 512u)
#define SMEM_TOTAL (SM_MBAR + 64u)   // 98880

// ---------------- scratch (no allocations allowed) ----------------
__device__ int    g_is64;
// panel-major pre-swizzled fp16 tiles:
// block (panel p, stage s) at ((p*NSTEPS)+s)*TILE_HALFS; inside: row r (0..127),
// 16B chunk j (0..7) at byte r*128 + ((j*16) ^ ((r&7)<<4))   [SW128]
__device__ __align__(128) __half g_Wh[(size_t)V_ * H_];   // 131 MB
__device__ __align__(128) __half g_Xh[(size_t)M_ * H_];   // 16 MB
__device__ float  g_pmax[(size_t)M_ * NTN];
__device__ float  g_psum[(size_t)M_ * NTN];
__device__ float  g_tok [M_];
__device__ float  g_losspt[M_];
__device__ float  g_klpt  [M_];
__device__ float  g_clippt[M_];
__device__ float  g_maskpt[M_];

// ---------------- kernel 0: detect int32 vs int64 input_id ----------------
__global__ void detect_id64_kernel(const int* __restrict__ idw) {
    __shared__ int bad;
    if (threadIdx.x == 0) bad = 0;
    __syncthreads();
    int local = 0;
    for (int i = threadIdx.x; i < 2048; i += blockDim.x)
        if (idw[2 * i + 1] != 0) local = 1;
    if (local) atomicOr(&bad, 1);
    __syncthreads();
    if (threadIdx.x == 0) g_is64 = bad ? 0 : 1;
}

// ---------------- kernel 0a: fp32 -> fp16 panel-swizzled convert ----------------
// one thread = one 16B chunk (8 halfs); H assumed 2048, panels of 128 rows.
__global__ void convert_panel_kernel(const float* __restrict__ src,
                                     __half* __restrict__ dst, int n8)
{
    const int i = blockIdx.x * blockDim.x + threadIdx.x;
    if (i >= n8) return;
    const float4* s = (const float4*)src + 2 * (size_t)i;
    float4 a = s[0], b = s[1];
    __half2 h[4];
    h[0] = __floats2half2_rn(a.x, a.y);
    h[1] = __floats2half2_rn(a.z, a.w);
    h[2] = __floats2half2_rn(b.x, b.y);
    h[3] = __floats2half2_rn(b.z, b.w);
    const long long base = 8LL * i;
    const int row = (int)(base / H_);
    const int k   = (int)(base % H_);
    const int p = row >> 7, r = row & 127;
    const int st = k >> 6, j = (k & 63) >> 3;
    const size_t off = ((size_t)(p * NSTEPS + st) << 14)
                     + (uint32_t)(r * 128 + ((j * 16) ^ ((r & 7) << 4)));
    *(uint4*)((char*)dst + off) = *(uint4*)h;
}

// ---------------- kernel 0b: exact fp32 target-token logits ----------------
__global__ void tok_logit_kernel(const float* __restrict__ X,
                                 const float* __restrict__ W,
                                 const float* __restrict__ bias,
                                 const void* __restrict__ idptr)
{
    const int warp = threadIdx.x >> 5, lane = threadIdx.x & 31;
    const int t = blockIdx.x * 8 + warp;
    if (t >= M_) return;
    const int vid = g_is64 ? (int)((const long long*)idptr)[t]
                           : ((const int*)idptr)[t];
    const float4* xr = (const float4*)(X + (size_t)t * H_);
    const float4* wr = (const float4*)(W + (size_t)vid * H_);
    float s = 0.f;
#pragma unroll 4
    for (int i = lane; i < H_ / 4; i += 32) {
        float4 a = xr[i], b = wr[i];
        s += a.x * b.x + a.y * b.y + a.z * b.z + a.w * b.w;
    }
#pragma unroll
    for (int o = 16; o; o >>= 1) s += __shfl_xor_sync(0xffffffffu, s, o);
    if (lane == 0) g_tok[t] = s + bias[vid];
}

// ---------------- ptx helpers ----------------
__device__ __forceinline__ void mma_f16(float* d, const uint32_t* a, const uint32_t* b) {
    asm volatile(
        "mma.sync.aligned.m16n8k16.row.col.f32.f16.f16.f32 "
        "{%0,%1,%2,%3}, {%4,%5,%6,%7}, {%8,%9}, {%0,%1,%2,%3};"
        : "+f"(d[0]), "+f"(d[1]), "+f"(d[2]), "+f"(d[3])
        : "r"(a[0]), "r"(a[1]), "r"(a[2]), "r"(a[3]), "r"(b[0]), "r"(b[1]));
}
__device__ __forceinline__ void ldsm_x4(uint32_t addr, uint32_t* r) {
    asm volatile("ldmatrix.sync.aligned.m8n8.x4.shared.b16 {%0,%1,%2,%3}, [%4];"
        : "=r"(r[0]), "=r"(r[1]), "=r"(r[2]), "=r"(r[3]) : "r"(addr));
}
__device__ __forceinline__ uint32_t cvta_smem(const void* p) {
    uint32_t a;
    asm("{ .reg .u64 t; cvta.to.shared.u64 t, %1; cvt.u32.u64 %0, t; }" : "=r"(a) : "l"(p));
    return a;
}
__device__ __forceinline__ void mbar_init(uint32_t a, uint32_t cnt) {
    asm volatile("mbarrier.init.shared.b64 [%0], %1;" :: "r"(a), "r"(cnt) : "memory");
}
__device__ __forceinline__ void mbar_expect(uint32_t a, uint32_t bytes) {
    asm volatile("mbarrier.arrive.expect_tx.shared.b64 _, [%0], %1;"
        :: "r"(a), "r"(bytes) : "memory");
}
__device__ __forceinline__ void mbar_wait(uint32_t a, uint32_t ph) {
    asm volatile("{\n\t.reg .pred P;\n\t"
        "W%=:\n\t"
        "mbarrier.try_wait.parity.acquire.cta.shared::cta.b64 P, [%0], %1, 0x989680;\n\t"
        "@P bra.uni D%=;\n\t"
        "bra.uni W%=;\n\t"
        "D%=:\n\t}" :: "r"(a), "r"(ph) : "memory");
}
__device__ __forceinline__ void fence_async_smem() {
    asm volatile("fence.proxy.async.shared::cta;" ::: "memory");
}
__device__ __forceinline__ void bulk_cp(uint32_t dst, const void* src,
                                        uint32_t bytes, uint32_t mbar) {
    asm volatile(
        "cp.async.bulk.shared::cta.global.mbarrier::complete_tx::bytes [%0], [%1], %2, [%3];"
        :: "r"(dst), "l"(src), "r"(bytes), "r"(mbar) : "memory");
}

// ---------------- kernel 1: fp16 mma GEMM + streaming LSE ----------------
// 256 threads (8 warps, warp tile 64x32). Stage fill = 2 cp.async.bulk of a
// pre-swizzled 16KB panel tile (vs 1024 LDGSTS) -> LSU freed for LDSM.
// Fragment values and k-order identical to Round 9/10 (bit-identical output).
__global__ void __launch_bounds__(256, 2)
gemm_lse_mma(const float* __restrict__ bias)
{
    extern __shared__ __align__(1024) char smem[];
    float* sbias = (float*)(smem + SM_BIAS);
    const uint32_t sb = cvta_smem(smem);

    const int tid = threadIdx.x, wid = tid >> 5, lid = tid & 31;
    const int g = lid >> 2, c = lid & 3;
    const int m0 = blockIdx.x * TM, n0 = blockIdx.y * TN;
    const int wm = (wid & 1) * 64;       // warp M offset (0/64)
    const int wni = wid >> 1;            // 0..3
    const int wn = wni * 32;             // warp N offset

    if (tid < 128) sbias[tid] = bias[n0 + tid];

    // mbarriers (one per stage)
    const uint32_t mb0 = sb + SM_MBAR;
    if (tid == 0) {
        mbar_init(mb0 + 0, 1); mbar_init(mb0 + 8, 1); mbar_init(mb0 + 16, 1);
        fence_async_smem();
    }
    __syncthreads();

    // ldmatrix addressing in the swizzled 128B-row layout:
    // byte(row, kbyte) = row*128 + (kbyte ^ ((row&7)<<4)); row&7 == lrow.
    const int lrow = lid & 7;
    const int lm8  = (lid >> 3) & 1;
    const int lk8  = (lid >> 4) & 1;
    const uint32_t sw = (uint32_t)(lrow << 4);
    uint32_t kx[4];
#pragma unroll
    for (int ks = 0; ks < 4; ks++)
        kx[ks] = ((uint32_t)(ks * 32 + lk8 * 16)) ^ sw;
    uint32_t aRow[4], bRow[2];
#pragma unroll
    for (int mf = 0; mf < 4; mf++)
        aRow[mf] = sb + (uint32_t)((wm + mf * 16 + lrow + lm8 * 8) * 128);
#pragma unroll
    for (int p = 0; p < 2; p++)
        bRow[p] = sb + TILE_BYTES + (uint32_t)((wn + p * 16 + lrow + lm8 * 8) * 128);

    // panel sources
    const __half* gA = g_Xh + (size_t)blockIdx.x * NSTEPS * TILE_HALFS;
    const __half* gB = g_Wh + (size_t)blockIdx.y * NSTEPS * TILE_HALFS;

    float acc[4][4][4];
#pragma unroll
    for (int mf = 0; mf < 4; mf++)
#pragma unroll
        for (int nf = 0; nf < 4; nf++)
#pragma unroll
            for (int q = 0; q < 4; q++) acc[mf][nf][q] = 0.f;

    // prologue: fill stages 0 and 1
    if (tid == 0) {
#pragma unroll
        for (int s = 0; s < 2; s++) {
            const uint32_t stb = sb + (uint32_t)s * STAGE_BYTES;
            mbar_expect(mb0 + 8u * s, STAGE_BYTES);
            bulk_cp(stb,              gA + (size_t)s * TILE_HALFS, TILE_BYTES, mb0 + 8u * s);
            bulk_cp(stb + TILE_BYTES, gB + (size_t)s * TILE_HALFS, TILE_BYTES, mb0 + 8u * s);
        }
    }

    int slot = 0, fslot = 2, phase = 0;

    for (int kt = 0; kt < NSTEPS; kt++) {
        mbar_wait(mb0 + 8u * slot, (uint32_t)phase);

        // fill kt+2 into fslot (its readers retired at end-of-(kt-1) barrier)
        if (tid == 0 && kt + 2 < NSTEPS) {
            const uint32_t stb = sb + (uint32_t)fslot * STAGE_BYTES;
            mbar_expect(mb0 + 8u * fslot, STAGE_BYTES);
            bulk_cp(stb,              gA + (size_t)(kt + 2) * TILE_HALFS, TILE_BYTES, mb0 + 8u * fslot);
            bulk_cp(stb + TILE_BYTES, gB + (size_t)(kt + 2) * TILE_HALFS, TILE_BYTES, mb0 + 8u * fslot);
        }

        const uint32_t stoff = (uint32_t)slot * STAGE_BYTES;
#pragma unroll
        for (int ks = 0; ks < 4; ks++) {       // 4 x k16 per 64-half stage
            uint32_t af[4][4], bf[4][2];
#pragma unroll
            for (int mf = 0; mf < 4; mf++)
                ldsm_x4(aRow[mf] + stoff + kx[ks], af[mf]);
#pragma unroll
            for (int p = 0; p < 2; p++) {
                uint32_t r[4];
                ldsm_x4(bRow[p] + stoff + kx[ks], r);
                bf[2 * p][0] = r[0];  bf[2 * p + 1][0] = r[1];
                bf[2 * p][1] = r[2];  bf[2 * p + 1][1] = r[3];
            }
#pragma unroll
            for (int mf = 0; mf < 4; mf++)
#pragma unroll
                for (int nf = 0; nf < 4; nf++)
                    mma_f16(acc[mf][nf], af[mf], bf[nf]);
        }
        __syncthreads();    // all reads of `slot` done before its next refill
        if (++slot == NSTAGE) { slot = 0; phase ^= 1; }
        if (++fslot == NSTAGE) fslot = 0;
    }

    // ---- epilogue: per-row bias + (max, sumexp) over warp's 32 cols ----
    const int tn = blockIdx.y * 4 + wni;
#pragma unroll
    for (int mf = 0; mf < 4; mf++) {
#pragma unroll
        for (int rh = 0; rh < 2; rh++) {
            const int row = m0 + wm + mf * 16 + g + rh * 8;
            float vals[8];
            float mx = -CUDART_INF_F;
#pragma unroll
            for (int nf = 0; nf < 4; nf++)
#pragma unroll
                for (int b = 0; b < 2; b++) {
                    const float v = acc[mf][nf][rh * 2 + b] + sbias[wn + nf * 8 + 2 * c + b];
                    vals[nf * 2 + b] = v;
                    mx = fmaxf(mx, v);
                }
            mx = fmaxf(mx, __shfl_xor_sync(0xffffffffu, mx, 1));
            mx = fmaxf(mx, __shfl_xor_sync(0xffffffffu, mx, 2));
            float s = 0.f;
#pragma unroll
            for (int j = 0; j < 8; j++) s += __expf(vals[j] - mx);
            s += __shfl_xor_sync(0xffffffffu, s, 1);
            s += __shfl_xor_sync(0xffffffffu, s, 2);
            if (c == 0) {
                g_pmax[(size_t)row * NTN + tn] = mx;
                g_psum[(size_t)row * NTN + tn] = s;
            }
        }
    }
}

// ---------------- kernel 2: combine partials, per-token GRPO terms ----------------
__global__ void combine_kernel(const int* __restrict__ amask,
                               const float* __restrict__ adv,
                               const float* __restrict__ ref,
                               const float* __restrict__ oldlp,
                               float* __restrict__ out)
{
    const int warp = threadIdx.x >> 5;
    const int lane = threadIdx.x & 31;
    const int t = blockIdx.x * 8 + warp;
    if (t >= M_) return;

    const float* pm = g_pmax + (size_t)t * NTN;
    const float* ps = g_psum + (size_t)t * NTN;
    float M = -CUDART_INF_F;
    for (int j = lane; j < NTN; j += 32) M = fmaxf(M, pm[j]);
#pragma unroll
    for (int o = 16; o; o >>= 1) M = fmaxf(M, __shfl_xor_sync(0xffffffffu, M, o));
    float S = 0.f;
    for (int j = lane; j < NTN; j += 32) S += ps[j] * expf(pm[j] - M);
#pragma unroll
    for (int o = 16; o; o >>= 1) S += __shfl_xor_sync(0xffffffffu, S, o);

    if (lane == 0) {
        const float lse  = M + logf(S);
        const float logp = g_tok[t] - lse;
        out[1 + t] = logp;

        const float mask = (float)amask[t];
        const float a    = adv[t / T_];
        const float d    = ref[t] - logp;
        const float kl   = expf(d) - d - 1.f;
        const float c1   = expf(logp - oldlp[t]);
        const float c2   = fminf(fmaxf(c1, 0.8f), 1.2f);
        const float l1   = c1 * a, l2 = c2 * a;
        const float ptl  = -(fminf(l1, l2) - 0.04f * kl);
        g_losspt[t] = ptl * mask;
        g_klpt  [t] = kl  * mask;
        g_clippt[t] = (l1 < l2 ? 1.f : 0.f) * mask;
        g_maskpt[t] = mask;
    }
}

// ---------------- kernel 3: deterministic final reductions ----------------
__global__ void finalize_kernel(float* __restrict__ out, int out_size)
{
    __shared__ float sl[1024], sk[1024], sc[1024], sm[1024];
    const int t = threadIdx.x;
    float l = 0.f, k = 0.f, c = 0.f, m = 0.f;
    for (int i = t; i < M_; i += 1024) {
        l += g_losspt[i]; k += g_klpt[i]; c += g_clippt[i]; m += g_maskpt[i];
    }
    sl[t] = l; sk[t] = k; sc[t] = c; sm[t] = m;
    __syncthreads();
    for (int s = 512; s; s >>= 1) {
        if (t < s) { sl[t]+=sl[t+s]; sk[t]+=sk[t+s]; sc[t]+=sc[t+s]; sm[t]+=sm[t+s]; }
        __syncthreads();
    }
    if (t == 0) {
        out[0]      = sl[0] / sm[0];
        out[M_ + 1] = sk[0] / sm[0];
        out[M_ + 2] = sc[0] / sm[0];
    }
    for (int i = M_ + 3 + t; i < out_size; i += 1024) out[i] = 0.f;
}

// ---------------- launch ----------------
extern "C" void kernel_launch(void* const* d_in, const int* in_sizes, int n_in,
                              void* d_out, int out_size)
{
    const float* x     = (const float*)d_in[0];
    const float* w     = (const float*)d_in[1];
    const float* bias  = (const float*)d_in[2];
    const void*  ids   = d_in[3];
    const int*   amask = (const int*)d_in[4];
    const float* adv   = (const float*)d_in[5];
    const float* ref   = (const float*)d_in[6];
    const float* oldlp = (const float*)d_in[7];
    float* out = (float*)d_out;

    cudaFuncSetAttribute(gemm_lse_mma, cudaFuncAttributeMaxDynamicSharedMemorySize,
                         (int)SMEM_TOTAL);

    detect_id64_kernel<<<1, 256>>>((const int*)ids);

    // fp32 -> fp16 panel-swizzled copies of W and X
    {
        __half* wh; cudaGetSymbolAddress((void**)&wh, g_Wh);
        __half* xh; cudaGetSymbolAddress((void**)&xh, g_Xh);
        const int wn8 = (V_ * H_) / 8, xn8 = (M_ * H_) / 8;
        convert_panel_kernel<<<(wn8 + 511) / 512, 512>>>(w, wh, wn8);
        convert_panel_kernel<<<(xn8 + 511) / 512, 512>>>(x, xh, xn8);
    }

    tok_logit_kernel<<<M_ / 8, 256>>>(x, w, bias, ids);

    dim3 grid(GRIDM, GRIDN);    // x fast -> consecutive CTAs share W panel in L2
    gemm_lse_mma<<<grid, 256, SMEM_TOTAL>>>(bias);

    combine_kernel<<<M_ / 8, 256>>>(amask, adv, ref, oldlp, out);
    finalize_kernel<<<1, 1024>>>(out, out_size);
}

// round 12
// speedup vs baseline: 1.4636x; 1.4636x over previous
#include <cuda_runtime.h>
#include <cuda_fp16.h>
#include <math_constants.h>
#include <cstdint>

// ---------------- problem constants ----------------
#define B_  4
#define T_  1024
#define M_  4096          // B*T tokens
#define H_  2048
#define V_  32000

// ---------------- GEMM tiling ----------------
#define TM  128           // CTA M tile
#define TN  128           // CTA N tile (2 CTAs/SM)
#define KCH 64            // K halfs per smem stage (128B rows)
#define NSTEPS (H_/KCH)   // 32
#define NSTAGE 3
#define GRIDM (M_/TM)     // 32
#define GRIDN (V_/TN)     // 250
#define NTN 1000          // 32-col LSE partial tiles (V/32)

#define TILE_BYTES 16384u            // 128 rows x 128B: one operand, one stage
#define TILE_HALFS 8192u
#define STAGE_BYTES (2u*TILE_BYTES)  // A + B = 32KB
#define SM_BIAS (NSTAGE*STAGE_BYTES) // 98304
#define SMEM_TOTAL (SM_BIAS + 128u*4u)   // 98816

// ---------------- scratch (no allocations allowed) ----------------
__device__ int    g_is64;
// panel-major pre-swizzled fp16 tiles:
// block (panel p, stage s) at ((p*NSTEPS)+s)*TILE_HALFS; inside: row r (0..127),
// 16B chunk j (0..7) at byte r*128 + ((j*16) ^ ((r&7)<<4))   [SW128-style]
__device__ __align__(128) __half g_Wh[(size_t)V_ * H_];   // 131 MB
__device__ __align__(128) __half g_Xh[(size_t)M_ * H_];   // 16 MB
__device__ float  g_pmax[(size_t)M_ * NTN];
__device__ float  g_psum[(size_t)M_ * NTN];
__device__ float  g_tok [M_];
__device__ float  g_losspt[M_];
__device__ float  g_klpt  [M_];
__device__ float  g_clippt[M_];
__device__ float  g_maskpt[M_];

// ---------------- kernel 0: detect int32 vs int64 input_id ----------------
__global__ void detect_id64_kernel(const int* __restrict__ idw) {
    __shared__ int bad;
    if (threadIdx.x == 0) bad = 0;
    __syncthreads();
    int local = 0;
    for (int i = threadIdx.x; i < 2048; i += blockDim.x)
        if (idw[2 * i + 1] != 0) local = 1;
    if (local) atomicOr(&bad, 1);
    __syncthreads();
    if (threadIdx.x == 0) g_is64 = bad ? 0 : 1;
}

// ---------------- kernel 0a: fp32 -> fp16 panel-swizzled convert ----------------
__global__ void convert_panel_kernel(const float* __restrict__ src,
                                     __half* __restrict__ dst, int n8)
{
    const int i = blockIdx.x * blockDim.x + threadIdx.x;
    if (i >= n8) return;
    const float4* s = (const float4*)src + 2 * (size_t)i;
    float4 a = s[0], b = s[1];
    __half2 h[4];
    h[0] = __floats2half2_rn(a.x, a.y);
    h[1] = __floats2half2_rn(a.z, a.w);
    h[2] = __floats2half2_rn(b.x, b.y);
    h[3] = __floats2half2_rn(b.z, b.w);
    const long long base = 8LL * i;
    const int row = (int)(base / H_);
    const int k   = (int)(base % H_);
    const int p = row >> 7, r = row & 127;
    const int st = k >> 6, j = (k & 63) >> 3;
    const size_t off = ((size_t)(p * NSTEPS + st) << 14)
                     + (uint32_t)(r * 128 + ((j * 16) ^ ((r & 7) << 4)));
    *(uint4*)((char*)dst + off) = *(uint4*)h;
}

// ---------------- kernel 0b: exact fp32 target-token logits ----------------
__global__ void tok_logit_kernel(const float* __restrict__ X,
                                 const float* __restrict__ W,
                                 const float* __restrict__ bias,
                                 const void* __restrict__ idptr)
{
    const int warp = threadIdx.x >> 5, lane = threadIdx.x & 31;
    const int t = blockIdx.x * 8 + warp;
    if (t >= M_) return;
    const int vid = g_is64 ? (int)((const long long*)idptr)[t]
                           : ((const int*)idptr)[t];
    const float4* xr = (const float4*)(X + (size_t)t * H_);
    const float4* wr = (const float4*)(W + (size_t)vid * H_);
    float s = 0.f;
#pragma unroll 4
    for (int i = lane; i < H_ / 4; i += 32) {
        float4 a = xr[i], b = wr[i];
        s += a.x * b.x + a.y * b.y + a.z * b.z + a.w * b.w;
    }
#pragma unroll
    for (int o = 16; o; o >>= 1) s += __shfl_xor_sync(0xffffffffu, s, o);
    if (lane == 0) g_tok[t] = s + bias[vid];
}

// ---------------- ptx helpers ----------------
__device__ __forceinline__ void mma_f16(float* d, const uint32_t* a, const uint32_t* b) {
    asm volatile(
        "mma.sync.aligned.m16n8k16.row.col.f32.f16.f16.f32 "
        "{%0,%1,%2,%3}, {%4,%5,%6,%7}, {%8,%9}, {%0,%1,%2,%3};"
        : "+f"(d[0]), "+f"(d[1]), "+f"(d[2]), "+f"(d[3])
        : "r"(a[0]), "r"(a[1]), "r"(a[2]), "r"(a[3]), "r"(b[0]), "r"(b[1]));
}
__device__ __forceinline__ void ldsm_x4(uint32_t addr, uint32_t* r) {
    asm volatile("ldmatrix.sync.aligned.m8n8.x4.shared.b16 {%0,%1,%2,%3}, [%4];"
        : "=r"(r[0]), "=r"(r[1]), "=r"(r[2]), "=r"(r[3]) : "r"(addr));
}
__device__ __forceinline__ uint32_t cvta_smem(const void* p) {
    uint32_t a;
    asm("{ .reg .u64 t; cvta.to.shared.u64 t, %1; cvt.u32.u64 %0, t; }" : "=r"(a) : "l"(p));
    return a;
}
__device__ __forceinline__ void cp16(uint32_t dst, const void* src) {
    asm volatile("cp.async.cg.shared.global [%0], [%1], 16;" :: "r"(dst), "l"(src));
}
__device__ __forceinline__ void cp_commit() {
    asm volatile("cp.async.commit_group;" ::: "memory");
}
__device__ __forceinline__ void cp_wait1() {
    asm volatile("cp.async.wait_group 1;" ::: "memory");
}

// ---------------- kernel 1: fp16 mma GEMM + streaming LSE ----------------
// 256 threads (8 warps, warp tile 64x32), 2 CTAs/SM, 3-stage cp.async ring
// over pre-swizzled contiguous 16KB panel tiles (KCH=64: half the barriers
// of Round 10). Fragment values + k-order unchanged -> bit-identical output.
__global__ void __launch_bounds__(256, 2)
gemm_lse_mma(const float* __restrict__ bias)
{
    extern __shared__ __align__(1024) char smem[];
    float* sbias = (float*)(smem + SM_BIAS);
    const uint32_t sb = cvta_smem(smem);

    const int tid = threadIdx.x, wid = tid >> 5, lid = tid & 31;
    const int g = lid >> 2, c = lid & 3;
    const int m0 = blockIdx.x * TM, n0 = blockIdx.y * TN;
    const int wm = (wid & 1) * 64;       // warp M offset (0/64)
    const int wni = wid >> 1;            // 0..3
    const int wn = wni * 32;             // warp N offset

    if (tid < 128) sbias[tid] = bias[n0 + tid];

    // ldmatrix addressing in the swizzled 128B-row layout:
    // byte(row, kbyte) = row*128 + (kbyte ^ ((row&7)<<4))
    const int lrow = lid & 7;
    const int lm8  = (lid >> 3) & 1;
    const int lk8  = (lid >> 4) & 1;
    const uint32_t sw = (uint32_t)(lrow << 4);
    uint32_t kx[4];
#pragma unroll
    for (int ks = 0; ks < 4; ks++)
        kx[ks] = ((uint32_t)(ks * 32 + lk8 * 16)) ^ sw;
    uint32_t aRow[4], bRow[2];
#pragma unroll
    for (int mf = 0; mf < 4; mf++)
        aRow[mf] = sb + (uint32_t)((wm + mf * 16 + lrow + lm8 * 8) * 128);
#pragma unroll
    for (int p = 0; p < 2; p++)
        bRow[p] = sb + TILE_BYTES + (uint32_t)((wn + p * 16 + lrow + lm8 * 8) * 128);

    // producers: contiguous 16KB tile copies; thread tid moves 4 chunks per
    // operand per stage at byte offsets tid*16 + i*4096 (identical src/dst).
    const char* gA = (const char*)(g_Xh + (size_t)blockIdx.x * NSTEPS * TILE_HALFS);
    const char* gB = (const char*)(g_Wh + (size_t)blockIdx.y * NSTEPS * TILE_HALFS);
    const uint32_t tof = (uint32_t)tid * 16u;

    float acc[4][4][4];
#pragma unroll
    for (int mf = 0; mf < 4; mf++)
#pragma unroll
        for (int nf = 0; nf < 4; nf++)
#pragma unroll
            for (int q = 0; q < 4; q++) acc[mf][nf][q] = 0.f;

    // prologue: fill stages 0 and 1
#pragma unroll
    for (int s = 0; s < 2; s++) {
        const uint32_t stb = sb + (uint32_t)s * STAGE_BYTES;
        const char* srcA = gA + (size_t)s * TILE_BYTES;
        const char* srcB = gB + (size_t)s * TILE_BYTES;
#pragma unroll
        for (int i = 0; i < 4; i++) {
            cp16(stb + tof + i * 4096u,              srcA + tof + i * 4096u);
            cp16(stb + TILE_BYTES + tof + i * 4096u, srcB + tof + i * 4096u);
        }
        cp_commit();
    }

    int slot = 0, fslot = 2;

    for (int kt = 0; kt < NSTEPS; kt++) {
        cp_wait1();
        __syncthreads();       // stage `slot` visible; slot `fslot` free

        if (kt + 2 < NSTEPS) {
            const uint32_t stb = sb + (uint32_t)fslot * STAGE_BYTES;
            const char* srcA = gA + (size_t)(kt + 2) * TILE_BYTES;
            const char* srcB = gB + (size_t)(kt + 2) * TILE_BYTES;
#pragma unroll
            for (int i = 0; i < 4; i++) {
                cp16(stb + tof + i * 4096u,              srcA + tof + i * 4096u);
                cp16(stb + TILE_BYTES + tof + i * 4096u, srcB + tof + i * 4096u);
            }
        }
        cp_commit();

        const uint32_t stoff = (uint32_t)slot * STAGE_BYTES;
#pragma unroll
        for (int ks = 0; ks < 4; ks++) {       // 4 x k16 per 64-half stage
            uint32_t af[4][4], bf[4][2];
#pragma unroll
            for (int mf = 0; mf < 4; mf++)
                ldsm_x4(aRow[mf] + stoff + kx[ks], af[mf]);
#pragma unroll
            for (int p = 0; p < 2; p++) {
                uint32_t r[4];
                ldsm_x4(bRow[p] + stoff + kx[ks], r);
                bf[2 * p][0] = r[0];  bf[2 * p + 1][0] = r[1];
                bf[2 * p][1] = r[2];  bf[2 * p + 1][1] = r[3];
            }
#pragma unroll
            for (int mf = 0; mf < 4; mf++)
#pragma unroll
                for (int nf = 0; nf < 4; nf++)
                    mma_f16(acc[mf][nf], af[mf], bf[nf]);
        }
        __syncthreads();    // all reads of `slot` done before its next refill
        if (++slot == NSTAGE) slot = 0;
        if (++fslot == NSTAGE) fslot = 0;
    }

    // ---- epilogue: per-row bias + (max, sumexp) over warp's 32 cols ----
    const int tn = blockIdx.y * 4 + wni;
#pragma unroll
    for (int mf = 0; mf < 4; mf++) {
#pragma unroll
        for (int rh = 0; rh < 2; rh++) {
            const int row = m0 + wm + mf * 16 + g + rh * 8;
            float vals[8];
            float mx = -CUDART_INF_F;
#pragma unroll
            for (int nf = 0; nf < 4; nf++)
#pragma unroll
                for (int b = 0; b < 2; b++) {
                    const float v = acc[mf][nf][rh * 2 + b] + sbias[wn + nf * 8 + 2 * c + b];
                    vals[nf * 2 + b] = v;
                    mx = fmaxf(mx, v);
                }
            mx = fmaxf(mx, __shfl_xor_sync(0xffffffffu, mx, 1));
            mx = fmaxf(mx, __shfl_xor_sync(0xffffffffu, mx, 2));
            float s = 0.f;
#pragma unroll
            for (int j = 0; j < 8; j++) s += __expf(vals[j] - mx);
            s += __shfl_xor_sync(0xffffffffu, s, 1);
            s += __shfl_xor_sync(0xffffffffu, s, 2);
            if (c == 0) {
                g_pmax[(size_t)row * NTN + tn] = mx;
                g_psum[(size_t)row * NTN + tn] = s;
            }
        }
    }
}

// ---------------- kernel 2: combine partials, per-token GRPO terms ----------------
__global__ void combine_kernel(const int* __restrict__ amask,
                               const float* __restrict__ adv,
                               const float* __restrict__ ref,
                               const float* __restrict__ oldlp,
                               float* __restrict__ out)
{
    const int warp = threadIdx.x >> 5;
    const int lane = threadIdx.x & 31;
    const int t = blockIdx.x * 8 + warp;
    if (t >= M_) return;

    const float* pm = g_pmax + (size_t)t * NTN;
    const float* ps = g_psum + (size_t)t * NTN;
    float M = -CUDART_INF_F;
    for (int j = lane; j < NTN; j += 32) M = fmaxf(M, pm[j]);
#pragma unroll
    for (int o = 16; o; o >>= 1) M = fmaxf(M, __shfl_xor_sync(0xffffffffu, M, o));
    float S = 0.f;
    for (int j = lane; j < NTN; j += 32) S += ps[j] * expf(pm[j] - M);
#pragma unroll
    for (int o = 16; o; o >>= 1) S += __shfl_xor_sync(0xffffffffu, S, o);

    if (lane == 0) {
        const float lse  = M + logf(S);
        const float logp = g_tok[t] - lse;
        out[1 + t] = logp;

        const float mask = (float)amask[t];
        const float a    = adv[t / T_];
        const float d    = ref[t] - logp;
        const float kl   = expf(d) - d - 1.f;
        const float c1   = expf(logp - oldlp[t]);
        const float c2   = fminf(fmaxf(c1, 0.8f), 1.2f);
        const float l1   = c1 * a, l2 = c2 * a;
        const float ptl  = -(fminf(l1, l2) - 0.04f * kl);
        g_losspt[t] = ptl * mask;
        g_klpt  [t] = kl  * mask;
        g_clippt[t] = (l1 < l2 ? 1.f : 0.f) * mask;
        g_maskpt[t] = mask;
    }
}

// ---------------- kernel 3: deterministic final reductions ----------------
__global__ void finalize_kernel(float* __restrict__ out, int out_size)
{
    __shared__ float sl[1024], sk[1024], sc[1024], sm[1024];
    const int t = threadIdx.x;
    float l = 0.f, k = 0.f, c = 0.f, m = 0.f;
    for (int i = t; i < M_; i += 1024) {
        l += g_losspt[i]; k += g_klpt[i]; c += g_clippt[i]; m += g_maskpt[i];
    }
    sl[t] = l; sk[t] = k; sc[t] = c; sm[t] = m;
    __syncthreads();
    for (int s = 512; s; s >>= 1) {
        if (t < s) { sl[t]+=sl[t+s]; sk[t]+=sk[t+s]; sc[t]+=sc[t+s]; sm[t]+=sm[t+s]; }
        __syncthreads();
    }
    if (t == 0) {
        out[0]      = sl[0] / sm[0];
        out[M_ + 1] = sk[0] / sm[0];
        out[M_ + 2] = sc[0] / sm[0];
    }
    for (int i = M_ + 3 + t; i < out_size; i += 1024) out[i] = 0.f;
}

// ---------------- launch ----------------
extern "C" void kernel_launch(void* const* d_in, const int* in_sizes, int n_in,
                              void* d_out, int out_size)
{
    const float* x     = (const float*)d_in[0];
    const float* w     = (const float*)d_in[1];
    const float* bias  = (const float*)d_in[2];
    const void*  ids   = d_in[3];
    const int*   amask = (const int*)d_in[4];
    const float* adv   = (const float*)d_in[5];
    const float* ref   = (const float*)d_in[6];
    const float* oldlp = (const float*)d_in[7];
    float* out = (float*)d_out;

    cudaFuncSetAttribute(gemm_lse_mma, cudaFuncAttributeMaxDynamicSharedMemorySize,
                         (int)SMEM_TOTAL);

    detect_id64_kernel<<<1, 256>>>((const int*)ids);

    // fp32 -> fp16 panel-swizzled copies of W and X
    {
        __half* wh; cudaGetSymbolAddress((void**)&wh, g_Wh);
        __half* xh; cudaGetSymbolAddress((void**)&xh, g_Xh);
        const int wn8 = (V_ * H_) / 8, xn8 = (M_ * H_) / 8;
        convert_panel_kernel<<<(wn8 + 511) / 512, 512>>>(w, wh, wn8);
        convert_panel_kernel<<<(xn8 + 511) / 512, 512>>>(x, xh, xn8);
    }

    tok_logit_kernel<<<M_ / 8, 256>>>(x, w, bias, ids);

    dim3 grid(GRIDM, GRIDN);    // x fast -> consecutive CTAs share W panel in L2
    gemm_lse_mma<<<grid, 256, SMEM_TOTAL>>>(bias);

    combine_kernel<<<M_ / 8, 256>>>(amask, adv, ref, oldlp, out);
    finalize_kernel<<<1, 1024>>>(out, out_size);
}

// round 13
// speedup vs baseline: 1.4817x; 1.0123x over previous
#include <cuda_runtime.h>
#include <cuda_fp16.h>
#include <math_constants.h>
#include <cstdint>

// ---------------- problem constants ----------------
#define B_  4
#define T_  1024
#define M_  4096          // B*T tokens
#define H_  2048
#define V_  32000

// ---------------- GEMM tiling ----------------
#define TM  128           // CTA M tile
#define TN  128           // CTA N tile (2 CTAs/SM)
#define KCH 64            // K halfs per smem stage (128B rows)
#define NSTEPS (H_/KCH)   // 32
#define NSTAGE 3
#define GRIDM (M_/TM)     // 32
#define GRIDN (V_/TN)     // 250
#define NTN 1000          // 32-col LSE partial tiles (V/32)

#define TILE_BYTES 16384u            // 128 rows x 128B: one operand, one stage
#define TILE_HALFS 8192u
#define STAGE_BYTES (2u*TILE_BYTES)  // A + B = 32KB
#define SM_BIAS (NSTAGE*STAGE_BYTES) // 98304
#define SMEM_TOTAL (SM_BIAS + 128u*4u)   // 98816

// ---------------- scratch (no allocations allowed) ----------------
__device__ int    g_is64;
// panel-major pre-swizzled fp16 tiles:
// block (panel p, stage s) at ((p*NSTEPS)+s)*TILE_HALFS; inside: row r (0..127),
// 16B chunk j (0..7) at byte r*128 + ((j*16) ^ ((r&7)<<4))   [SW128-style]
__device__ __align__(128) __half g_Wh[(size_t)V_ * H_];   // 131 MB
__device__ __align__(128) __half g_Xh[(size_t)M_ * H_];   // 16 MB
__device__ float  g_pmax[(size_t)M_ * NTN];
__device__ float  g_psum[(size_t)M_ * NTN];
__device__ float  g_tok [M_];
__device__ float  g_losspt[M_];
__device__ float  g_klpt  [M_];
__device__ float  g_clippt[M_];
__device__ float  g_maskpt[M_];

// ---------------- kernel 0: detect int32 vs int64 input_id ----------------
__global__ void detect_id64_kernel(const int* __restrict__ idw) {
    __shared__ int bad;
    if (threadIdx.x == 0) bad = 0;
    __syncthreads();
    int local = 0;
    for (int i = threadIdx.x; i < 2048; i += blockDim.x)
        if (idw[2 * i + 1] != 0) local = 1;
    if (local) atomicOr(&bad, 1);
    __syncthreads();
    if (threadIdx.x == 0) g_is64 = bad ? 0 : 1;
}

// ---------------- kernel 0a: fused fp32 -> fp16 panel-swizzled convert (W then X) ----------------
__global__ void convert_panel_kernel(const float* __restrict__ srcW,
                                     __half* __restrict__ dstW, int wn8,
                                     const float* __restrict__ srcX,
                                     __half* __restrict__ dstX, int xn8)
{
    int i = blockIdx.x * blockDim.x + threadIdx.x;
    const float* src; __half* dst;
    if (i < wn8) { src = srcW; dst = dstW; }
    else { i -= wn8; if (i >= xn8) return; src = srcX; dst = dstX; }

    const float4* s = (const float4*)src + 2 * (size_t)i;
    float4 a = s[0], b = s[1];
    __half2 h[4];
    h[0] = __floats2half2_rn(a.x, a.y);
    h[1] = __floats2half2_rn(a.z, a.w);
    h[2] = __floats2half2_rn(b.x, b.y);
    h[3] = __floats2half2_rn(b.z, b.w);
    const long long base = 8LL * i;
    const int row = (int)(base / H_);
    const int k   = (int)(base % H_);
    const int p = row >> 7, r = row & 127;
    const int st = k >> 6, j = (k & 63) >> 3;
    const size_t off = ((size_t)(p * NSTEPS + st) << 14)
                     + (uint32_t)(r * 128 + ((j * 16) ^ ((r & 7) << 4)));
    *(uint4*)((char*)dst + off) = *(uint4*)h;
}

// ---------------- kernel 0b: exact fp32 target-token logits ----------------
__global__ void tok_logit_kernel(const float* __restrict__ X,
                                 const float* __restrict__ W,
                                 const float* __restrict__ bias,
                                 const void* __restrict__ idptr)
{
    const int warp = threadIdx.x >> 5, lane = threadIdx.x & 31;
    const int t = blockIdx.x * 8 + warp;
    if (t >= M_) return;
    const int vid = g_is64 ? (int)((const long long*)idptr)[t]
                           : ((const int*)idptr)[t];
    const float4* xr = (const float4*)(X + (size_t)t * H_);
    const float4* wr = (const float4*)(W + (size_t)vid * H_);
    float s = 0.f;
#pragma unroll 4
    for (int i = lane; i < H_ / 4; i += 32) {
        float4 a = xr[i], b = wr[i];
        s += a.x * b.x + a.y * b.y + a.z * b.z + a.w * b.w;
    }
#pragma unroll
    for (int o = 16; o; o >>= 1) s += __shfl_xor_sync(0xffffffffu, s, o);
    if (lane == 0) g_tok[t] = s + bias[vid];
}

// ---------------- ptx helpers ----------------
__device__ __forceinline__ void mma_f16(float* d, const uint32_t* a, const uint32_t* b) {
    asm volatile(
        "mma.sync.aligned.m16n8k16.row.col.f32.f16.f16.f32 "
        "{%0,%1,%2,%3}, {%4,%5,%6,%7}, {%8,%9}, {%0,%1,%2,%3};"
        : "+f"(d[0]), "+f"(d[1]), "+f"(d[2]), "+f"(d[3])
        : "r"(a[0]), "r"(a[1]), "r"(a[2]), "r"(a[3]), "r"(b[0]), "r"(b[1]));
}
__device__ __forceinline__ void ldsm_x4(uint32_t addr, uint32_t* r) {
    asm volatile("ldmatrix.sync.aligned.m8n8.x4.shared.b16 {%0,%1,%2,%3}, [%4];"
        : "=r"(r[0]), "=r"(r[1]), "=r"(r[2]), "=r"(r[3]) : "r"(addr));
}
__device__ __forceinline__ uint32_t cvta_smem(const void* p) {
    uint32_t a;
    asm("{ .reg .u64 t; cvta.to.shared.u64 t, %1; cvt.u32.u64 %0, t; }" : "=r"(a) : "l"(p));
    return a;
}
__device__ __forceinline__ void cp16(uint32_t dst, const void* src) {
    asm volatile("cp.async.cg.shared.global [%0], [%1], 16;" :: "r"(dst), "l"(src));
}
__device__ __forceinline__ void cp_commit() {
    asm volatile("cp.async.commit_group;" ::: "memory");
}
__device__ __forceinline__ void cp_wait1() {
    asm volatile("cp.async.wait_group 1;" ::: "memory");
}

// ---------------- kernel 1: fp16 mma GEMM + streaming LSE ----------------
// 256 threads (8 warps, warp tile 64x32), 2 CTAs/SM, 3-stage cp.async ring
// over pre-swizzled contiguous 16KB panel tiles. ONE barrier per stage:
// the post-wait barrier in iteration kt already orders all compute(kt-1)
// reads of stage (kt-1)%3 before any fill of that same stage in kt.
// Fragment values + k-order unchanged -> bit-identical output.
__global__ void __launch_bounds__(256, 2)
gemm_lse_mma(const float* __restrict__ bias)
{
    extern __shared__ __align__(1024) char smem[];
    float* sbias = (float*)(smem + SM_BIAS);
    const uint32_t sb = cvta_smem(smem);

    const int tid = threadIdx.x, wid = tid >> 5, lid = tid & 31;
    const int g = lid >> 2, c = lid & 3;
    const int m0 = blockIdx.x * TM, n0 = blockIdx.y * TN;
    const int wm = (wid & 1) * 64;       // warp M offset (0/64)
    const int wni = wid >> 1;            // 0..3
    const int wn = wni * 32;             // warp N offset

    if (tid < 128) sbias[tid] = bias[n0 + tid];

    // ldmatrix addressing in the swizzled 128B-row layout:
    // byte(row, kbyte) = row*128 + (kbyte ^ ((row&7)<<4))
    const int lrow = lid & 7;
    const int lm8  = (lid >> 3) & 1;
    const int lk8  = (lid >> 4) & 1;
    const uint32_t sw = (uint32_t)(lrow << 4);
    uint32_t kx[4];
#pragma unroll
    for (int ks = 0; ks < 4; ks++)
        kx[ks] = ((uint32_t)(ks * 32 + lk8 * 16)) ^ sw;
    uint32_t aRow[4], bRow[2];
#pragma unroll
    for (int mf = 0; mf < 4; mf++)
        aRow[mf] = sb + (uint32_t)((wm + mf * 16 + lrow + lm8 * 8) * 128);
#pragma unroll
    for (int p = 0; p < 2; p++)
        bRow[p] = sb + TILE_BYTES + (uint32_t)((wn + p * 16 + lrow + lm8 * 8) * 128);

    // producers: contiguous 16KB tile copies; thread tid moves 4 chunks per
    // operand per stage at byte offsets tid*16 + i*4096 (identical src/dst).
    const char* gA = (const char*)(g_Xh + (size_t)blockIdx.x * NSTEPS * TILE_HALFS);
    const char* gB = (const char*)(g_Wh + (size_t)blockIdx.y * NSTEPS * TILE_HALFS);
    const uint32_t tof = (uint32_t)tid * 16u;

    float acc[4][4][4];
#pragma unroll
    for (int mf = 0; mf < 4; mf++)
#pragma unroll
        for (int nf = 0; nf < 4; nf++)
#pragma unroll
            for (int q = 0; q < 4; q++) acc[mf][nf][q] = 0.f;

    // prologue: fill stages 0 and 1
#pragma unroll
    for (int s = 0; s < 2; s++) {
        const uint32_t stb = sb + (uint32_t)s * STAGE_BYTES;
        const char* srcA = gA + (size_t)s * TILE_BYTES;
        const char* srcB = gB + (size_t)s * TILE_BYTES;
#pragma unroll
        for (int i = 0; i < 4; i++) {
            cp16(stb + tof + i * 4096u,              srcA + tof + i * 4096u);
            cp16(stb + TILE_BYTES + tof + i * 4096u, srcB + tof + i * 4096u);
        }
        cp_commit();
    }

    int slot = 0, fslot = 2;

    for (int kt = 0; kt < NSTEPS; kt++) {
        cp_wait1();
        __syncthreads();   // (1) stage `slot` data visible to all threads;
                           // (2) all compute(kt-1) reads of stage fslot done

        if (kt + 2 < NSTEPS) {
            const uint32_t stb = sb + (uint32_t)fslot * STAGE_BYTES;
            const char* srcA = gA + (size_t)(kt + 2) * TILE_BYTES;
            const char* srcB = gB + (size_t)(kt + 2) * TILE_BYTES;
#pragma unroll
            for (int i = 0; i < 4; i++) {
                cp16(stb + tof + i * 4096u,              srcA + tof + i * 4096u);
                cp16(stb + TILE_BYTES + tof + i * 4096u, srcB + tof + i * 4096u);
            }
        }
        cp_commit();

        const uint32_t stoff = (uint32_t)slot * STAGE_BYTES;
#pragma unroll
        for (int ks = 0; ks < 4; ks++) {       // 4 x k16 per 64-half stage
            uint32_t af[4][4], bf[4][2];
#pragma unroll
            for (int mf = 0; mf < 4; mf++)
                ldsm_x4(aRow[mf] + stoff + kx[ks], af[mf]);
#pragma unroll
            for (int p = 0; p < 2; p++) {
                uint32_t r[4];
                ldsm_x4(bRow[p] + stoff + kx[ks], r);
                bf[2 * p][0] = r[0];  bf[2 * p + 1][0] = r[1];
                bf[2 * p][1] = r[2];  bf[2 * p + 1][1] = r[3];
            }
#pragma unroll
            for (int mf = 0; mf < 4; mf++)
#pragma unroll
                for (int nf = 0; nf < 4; nf++)
                    mma_f16(acc[mf][nf], af[mf], bf[nf]);
        }
        // no trailing barrier: next iteration's barrier provides the ordering
        if (++slot == NSTAGE) slot = 0;
        if (++fslot == NSTAGE) fslot = 0;
    }

    // ---- epilogue: per-row bias + (max, sumexp) over warp's 32 cols ----
    const int tn = blockIdx.y * 4 + wni;
#pragma unroll
    for (int mf = 0; mf < 4; mf++) {
#pragma unroll
        for (int rh = 0; rh < 2; rh++) {
            const int row = m0 + wm + mf * 16 + g + rh * 8;
            float vals[8];
            float mx = -CUDART_INF_F;
#pragma unroll
            for (int nf = 0; nf < 4; nf++)
#pragma unroll
                for (int b = 0; b < 2; b++) {
                    const float v = acc[mf][nf][rh * 2 + b] + sbias[wn + nf * 8 + 2 * c + b];
                    vals[nf * 2 + b] = v;
                    mx = fmaxf(mx, v);
                }
            mx = fmaxf(mx, __shfl_xor_sync(0xffffffffu, mx, 1));
            mx = fmaxf(mx, __shfl_xor_sync(0xffffffffu, mx, 2));
            float s = 0.f;
#pragma unroll
            for (int j = 0; j < 8; j++) s += __expf(vals[j] - mx);
            s += __shfl_xor_sync(0xffffffffu, s, 1);
            s += __shfl_xor_sync(0xffffffffu, s, 2);
            if (c == 0) {
                g_pmax[(size_t)row * NTN + tn] = mx;
                g_psum[(size_t)row * NTN + tn] = s;
            }
        }
    }
}

// ---------------- kernel 2: combine partials, per-token GRPO terms ----------------
__global__ void combine_kernel(const int* __restrict__ amask,
                               const float* __restrict__ adv,
                               const float* __restrict__ ref,
                               const float* __restrict__ oldlp,
                               float* __restrict__ out)
{
    const int warp = threadIdx.x >> 5;
    const int lane = threadIdx.x & 31;
    const int t = blockIdx.x * 8 + warp;
    if (t >= M_) return;

    const float* pm = g_pmax + (size_t)t * NTN;
    const float* ps = g_psum + (size_t)t * NTN;
    float M = -CUDART_INF_F;
    for (int j = lane; j < NTN; j += 32) M = fmaxf(M, pm[j]);
#pragma unroll
    for (int o = 16; o; o >>= 1) M = fmaxf(M, __shfl_xor_sync(0xffffffffu, M, o));
    float S = 0.f;
    for (int j = lane; j < NTN; j += 32) S += ps[j] * expf(pm[j] - M);
#pragma unroll
    for (int o = 16; o; o >>= 1) S += __shfl_xor_sync(0xffffffffu, S, o);

    if (lane == 0) {
        const float lse  = M + logf(S);
        const float logp = g_tok[t] - lse;
        out[1 + t] = logp;

        const float mask = (float)amask[t];
        const float a    = adv[t / T_];
        const float d    = ref[t] - logp;
        const float kl   = expf(d) - d - 1.f;
        const float c1   = expf(logp - oldlp[t]);
        const float c2   = fminf(fmaxf(c1, 0.8f), 1.2f);
        const float l1   = c1 * a, l2 = c2 * a;
        const float ptl  = -(fminf(l1, l2) - 0.04f * kl);
        g_losspt[t] = ptl * mask;
        g_klpt  [t] = kl  * mask;
        g_clippt[t] = (l1 < l2 ? 1.f : 0.f) * mask;
        g_maskpt[t] = mask;
    }
}

// ---------------- kernel 3: deterministic final reductions ----------------
__global__ void finalize_kernel(float* __restrict__ out, int out_size)
{
    __shared__ float sl[1024], sk[1024], sc[1024], sm[1024];
    const int t = threadIdx.x;
    float l = 0.f, k = 0.f, c = 0.f, m = 0.f;
    for (int i = t; i < M_; i += 1024) {
        l += g_losspt[i]; k += g_klpt[i]; c += g_clippt[i]; m += g_maskpt[i];
    }
    sl[t] = l; sk[t] = k; sc[t] = c; sm[t] = m;
    __syncthreads();
    for (int s = 512; s; s >>= 1) {
        if (t < s) { sl[t]+=sl[t+s]; sk[t]+=sk[t+s]; sc[t]+=sc[t+s]; sm[t]+=sm[t+s]; }
        __syncthreads();
    }
    if (t == 0) {
        out[0]      = sl[0] / sm[0];
        out[M_ + 1] = sk[0] / sm[0];
        out[M_ + 2] = sc[0] / sm[0];
    }
    for (int i = M_ + 3 + t; i < out_size; i += 1024) out[i] = 0.f;
}

// ---------------- launch ----------------
extern "C" void kernel_launch(void* const* d_in, const int* in_sizes, int n_in,
                              void* d_out, int out_size)
{
    const float* x     = (const float*)d_in[0];
    const float* w     = (const float*)d_in[1];
    const float* bias  = (const float*)d_in[2];
    const void*  ids   = d_in[3];
    const int*   amask = (const int*)d_in[4];
    const float* adv   = (const float*)d_in[5];
    const float* ref   = (const float*)d_in[6];
    const float* oldlp = (const float*)d_in[7];
    float* out = (float*)d_out;

    cudaFuncSetAttribute(gemm_lse_mma, cudaFuncAttributeMaxDynamicSharedMemorySize,
                         (int)SMEM_TOTAL);

    detect_id64_kernel<<<1, 256>>>((const int*)ids);

    // fused fp32 -> fp16 panel-swizzled copies of W and X (one launch)
    {
        __half* wh; cudaGetSymbolAddress((void**)&wh, g_Wh);
        __half* xh; cudaGetSymbolAddress((void**)&xh, g_Xh);
        const int wn8 = (V_ * H_) / 8, xn8 = (M_ * H_) / 8;
        convert_panel_kernel<<<(wn8 + xn8 + 511) / 512, 512>>>(w, wh, wn8, x, xh, xn8);
    }

    tok_logit_kernel<<<M_ / 8, 256>>>(x, w, bias, ids);

    dim3 grid(GRIDM, GRIDN);    // x fast -> consecutive CTAs share W panel in L2
    gemm_lse_mma<<<grid, 256, SMEM_TOTAL>>>(bias);

    combine_kernel<<<M_ / 8, 256>>>(amask, adv, ref, oldlp, out);
    finalize_kernel<<<1, 1024>>>(out, out_size);
}